// round 13
// baseline (speedup 1.0000x reference)
#include <cuda_runtime.h>
#include <cuda_fp16.h>

// ---------------------------------------------------------------------------
// MutationAwareGNN R13: unified agg template with U4R (lanes/row) parameter.
// agg1/3: U4R=4 (8 nodes/warp)  — measured at L1tex wavefront floor.
// agg2:   U4R=8 (4 nodes/warp)  — full 128B row = 1 line = 1 wavefront/edge
// (fixes R12's SEGS split which cost 2 wf/edge). All aggs: guard-free 4-edge
// unroll, aligned int4 col prefetch, pairwise HADD2 pre-add, fp32 accumulate.
// Fill: 16 edges/thread. Bucket adjacency + zero-row sentinels.
// ---------------------------------------------------------------------------

#define NMAX 100000
#define EMAX 3200000
#define GMAX 256
#define CAP  128          // bucket capacity (Poisson(32) degrees: safe)

__device__ int    g_cnt[NMAX];
__device__ int    g_cnte4[NMAX];             // padded count, multiple of 4
__device__ int    g_col[(NMAX + 1) * CAP];   // +1 spare bucket absorbs over-reads
__device__ float  g_dinv[NMAX];
__device__ __half g_hA[(NMAX + 1) * 64];     // row n = zero sentinel (per layout)
__device__ __half g_hB[(NMAX + 1) * 64];

// ---------------------------- Bucket fill ----------------------------------

__global__ void k_fill(const int* __restrict__ src, const int* __restrict__ dst, int E) {
    int e16 = (blockIdx.x * blockDim.x + threadIdx.x) * 16;
    if (e16 + 15 < E) {
        int4 s[4], d[4];
#pragma unroll
        for (int q = 0; q < 4; q++) {
            s[q] = *reinterpret_cast<const int4*>(&src[e16 + q * 4]);
            d[q] = *reinterpret_cast<const int4*>(&dst[e16 + q * 4]);
        }
#pragma unroll
        for (int q = 0; q < 4; q++) {
            int p0 = atomicAdd(&g_cnt[d[q].x], 1);
            int p1 = atomicAdd(&g_cnt[d[q].y], 1);
            int p2 = atomicAdd(&g_cnt[d[q].z], 1);
            int p3 = atomicAdd(&g_cnt[d[q].w], 1);
            if (p0 < CAP) g_col[d[q].x * CAP + p0] = s[q].x;
            if (p1 < CAP) g_col[d[q].y * CAP + p1] = s[q].y;
            if (p2 < CAP) g_col[d[q].z * CAP + p2] = s[q].z;
            if (p3 < CAP) g_col[d[q].w * CAP + p3] = s[q].w;
        }
    } else {
        for (int e = e16; e < E; e++) {
            int dd = dst[e];
            int p = atomicAdd(&g_cnt[dd], 1);
            if (p < CAP) g_col[dd * CAP + p] = src[e];
        }
    }
}

// dinv + pad buckets to multiple of 4 with sentinel index n (zero row).
__global__ void k_dinv_pad(int n) {
    int i = blockIdx.x * blockDim.x + threadIdx.x;
    if (i >= n) return;
    int c   = min(g_cnt[i], CAP);
    int ce4 = (c + 3) & ~3;
    for (int s = c; s < ce4; s++) g_col[i * CAP + s] = n;  // sentinel -> zero row
    g_cnte4[i] = ce4;
    g_dinv[i]  = rsqrtf((float)(c + 1));                   // +1 self-loop
}

// ------------------------------ Prep (layer 1) ------------------------------
// g_hA rows 0..n-1 = dinv_j * x_j (25 features padded to 32 fp16); row n = 0.

__global__ void k_prep(const float* __restrict__ x, int n) {
    int i = blockIdx.x * blockDim.x + threadIdx.x;   // half2 slot
    if (i >= (n + 1) * 16) return;
    int node = i >> 4, f2 = i & 15;
    float a = 0.f, b = 0.f;
    if (node < n) {
        float d = g_dinv[node];
        int f = f2 * 2;
        a = (f     < 25) ? d * __ldg(&x[node * 25 + f])     : 0.f;
        b = (f + 1 < 25) ? d * __ldg(&x[node * 25 + f + 1]) : 0.f;
    }
    reinterpret_cast<__half2*>(g_hA)[i] = __floats2half2_rn(a, b);
}

// ----------------------------- Aggregation ---------------------------------
// U4R lanes cover one row (uint4 each); GPN = 32/U4R nodes per warp. Each
// group walks its node's bucket 4 edges per iteration, guard-free (buckets
// padded to mult 4, sentinel row n zero, aligned int4 col prefetch).
// Pairwise HADD2 pre-add (depth 1), fp32 across pairs.

template <int U4R, int RELU, int SRC>
__global__ void k_agg_g(const float* __restrict__ bias, int n) {
    constexpr int GPN = 32 / U4R;     // nodes per warp: 8 (U4R=4) or 4 (U4R=8)
    int wid  = (blockIdx.x * blockDim.x + threadIdx.x) >> 5;
    int lane = threadIdx.x & 31;
    int grp = lane / U4R;
    int sub = lane % U4R;
    int node = wid * GPN + grp;
    bool valid = node < n;
    int nd = valid ? node : n;        // sentinel row safe to gather

    const uint4* base = reinterpret_cast<const uint4*>(SRC ? g_hB : g_hA);
    __half*      db   = SRC ? g_hA : g_hB;

    // self-loop term
    float acc[8];
    {
        uint4 v = base[nd * U4R + sub];
        float2 f0 = __half22float2(*reinterpret_cast<__half2*>(&v.x));
        float2 f1 = __half22float2(*reinterpret_cast<__half2*>(&v.y));
        float2 f2 = __half22float2(*reinterpret_cast<__half2*>(&v.z));
        float2 f3 = __half22float2(*reinterpret_cast<__half2*>(&v.w));
        acc[0] = f0.x; acc[1] = f0.y; acc[2] = f1.x; acc[3] = f1.y;
        acc[4] = f2.x; acc[5] = f2.y; acc[6] = f3.x; acc[7] = f3.y;
    }

    int e    = node * CAP;
    int endv = e + (valid ? g_cnte4[node] : 0);
    int4 jj = *reinterpret_cast<const int4*>(&g_col[e]);
    while (e < endv) {
        uint4 v0 = base[jj.x * U4R + sub];
        uint4 v1 = base[jj.y * U4R + sub];
        uint4 v2 = base[jj.z * U4R + sub];
        uint4 v3 = base[jj.w * U4R + sub];
        e += 4;
        jj = *reinterpret_cast<const int4*>(&g_col[e]);   // prefetch (spare bucket)
        __half2 a0 = __hadd2(*reinterpret_cast<__half2*>(&v0.x), *reinterpret_cast<__half2*>(&v1.x));
        __half2 a1 = __hadd2(*reinterpret_cast<__half2*>(&v0.y), *reinterpret_cast<__half2*>(&v1.y));
        __half2 a2 = __hadd2(*reinterpret_cast<__half2*>(&v0.z), *reinterpret_cast<__half2*>(&v1.z));
        __half2 a3 = __hadd2(*reinterpret_cast<__half2*>(&v0.w), *reinterpret_cast<__half2*>(&v1.w));
        __half2 b0 = __hadd2(*reinterpret_cast<__half2*>(&v2.x), *reinterpret_cast<__half2*>(&v3.x));
        __half2 b1 = __hadd2(*reinterpret_cast<__half2*>(&v2.y), *reinterpret_cast<__half2*>(&v3.y));
        __half2 b2 = __hadd2(*reinterpret_cast<__half2*>(&v2.z), *reinterpret_cast<__half2*>(&v3.z));
        __half2 b3 = __hadd2(*reinterpret_cast<__half2*>(&v2.w), *reinterpret_cast<__half2*>(&v3.w));
        float2 fa0 = __half22float2(a0), fa1 = __half22float2(a1);
        float2 fa2 = __half22float2(a2), fa3 = __half22float2(a3);
        float2 fb0 = __half22float2(b0), fb1 = __half22float2(b1);
        float2 fb2 = __half22float2(b2), fb3 = __half22float2(b3);
        acc[0] += fa0.x + fb0.x; acc[1] += fa0.y + fb0.y;
        acc[2] += fa1.x + fb1.x; acc[3] += fa1.y + fb1.y;
        acc[4] += fa2.x + fb2.x; acc[5] += fa2.y + fb2.y;
        acc[6] += fa3.x + fb3.x; acc[7] += fa3.y + fb3.y;
    }

    if (valid) {
        float d = g_dinv[node];
        __half out[8];
#pragma unroll
        for (int k = 0; k < 8; k++) {
            float r;
            if (RELU) r = fmaxf(fmaf(acc[k], d, __ldg(&bias[sub * 8 + k])), 0.f);
            else      r = acc[k] * d;
            out[k] = __float2half_rn(r);
        }
        reinterpret_cast<uint4*>(db)[node * U4R + sub] = *reinterpret_cast<uint4*>(out);
    }
}

// ------------------------------- Dense GEMM --------------------------------
// 2 rows per thread. Block 0 writes the zero sentinel row n at the OUTPUT
// stride, so a following agg reading O sees zeros at index n.

template <int FINP, int FINW, int FOUT, int EPI, int SRC>
__global__ void k_gemm_h(const float* __restrict__ W, const float* __restrict__ bias, int n) {
    __shared__ float Wsh[FINP * FOUT];
    for (int i = threadIdx.x; i < FINP * FOUT; i += blockDim.x)
        Wsh[i] = (i < FINW * FOUT) ? W[i] : 0.f;
    __syncthreads();

    const __half* X = SRC ? g_hB : g_hA;
    __half*       O = SRC ? g_hA : g_hB;

    if (blockIdx.x == 0 && threadIdx.x < FOUT / 8) {   // zero sentinel row n
        reinterpret_cast<uint4*>(O)[(long)n * (FOUT / 8) + threadIdx.x] =
            make_uint4(0u, 0u, 0u, 0u);
    }

    constexpr int TPR  = FOUT / 4;
    constexpr int RPB  = 256 / TPR;
    constexpr int RPB2 = RPB * 2;
    int slot = (int)(threadIdx.x / TPR);
    int row0 = blockIdx.x * RPB2 + slot;
    int row1 = row0 + RPB;
    int fx = (threadIdx.x % TPR) * 4;
    bool v0 = row0 < n, v1 = row1 < n;
    if (!v0) return;

    const uint4* xr0 = reinterpret_cast<const uint4*>(X + (long)row0 * FINP);
    const uint4* xr1 = reinterpret_cast<const uint4*>(X + (long)(v1 ? row1 : row0) * FINP);
    float4 a0 = make_float4(0.f, 0.f, 0.f, 0.f);
    float4 a1 = make_float4(0.f, 0.f, 0.f, 0.f);
#pragma unroll
    for (int q = 0; q < FINP / 8; q++) {
        uint4 p0 = __ldg(&xr0[q]);
        uint4 p1 = __ldg(&xr1[q]);
        const unsigned* u0 = &p0.x;
        const unsigned* u1 = &p1.x;
#pragma unroll
        for (int t = 0; t < 4; t++) {
            float2 f0 = __half22float2(*reinterpret_cast<const __half2*>(&u0[t]));
            float2 f1 = __half22float2(*reinterpret_cast<const __half2*>(&u1[t]));
            int k = q * 8 + t * 2;
            float4 w0 = *reinterpret_cast<const float4*>(&Wsh[k * FOUT + fx]);
            float4 w1 = *reinterpret_cast<const float4*>(&Wsh[(k + 1) * FOUT + fx]);
            a0.x = fmaf(f0.x, w0.x, fmaf(f0.y, w1.x, a0.x));
            a0.y = fmaf(f0.x, w0.y, fmaf(f0.y, w1.y, a0.y));
            a0.z = fmaf(f0.x, w0.z, fmaf(f0.y, w1.z, a0.z));
            a0.w = fmaf(f0.x, w0.w, fmaf(f0.y, w1.w, a0.w));
            a1.x = fmaf(f1.x, w0.x, fmaf(f1.y, w1.x, a1.x));
            a1.y = fmaf(f1.x, w0.y, fmaf(f1.y, w1.y, a1.y));
            a1.z = fmaf(f1.x, w0.z, fmaf(f1.y, w1.z, a1.z));
            a1.w = fmaf(f1.x, w0.w, fmaf(f1.y, w1.w, a1.w));
        }
    }

    float bx = 0.f, by = 0.f, bz = 0.f, bw = 0.f;
    if (EPI == 1) {
        bx = __ldg(&bias[fx + 0]); by = __ldg(&bias[fx + 1]);
        bz = __ldg(&bias[fx + 2]); bw = __ldg(&bias[fx + 3]);
    }
    {
        float4 acc = a0;
        if (EPI == 0) {
            float d = g_dinv[row0];
            acc.x *= d; acc.y *= d; acc.z *= d; acc.w *= d;
        } else {
            acc.x = fmaxf(acc.x + bx, 0.f); acc.y = fmaxf(acc.y + by, 0.f);
            acc.z = fmaxf(acc.z + bz, 0.f); acc.w = fmaxf(acc.w + bw, 0.f);
        }
        __half2* op = reinterpret_cast<__half2*>(&O[(long)row0 * FOUT + fx]);
        op[0] = __floats2half2_rn(acc.x, acc.y);
        op[1] = __floats2half2_rn(acc.z, acc.w);
    }
    if (v1) {
        float4 acc = a1;
        if (EPI == 0) {
            float d = g_dinv[row1];
            acc.x *= d; acc.y *= d; acc.z *= d; acc.w *= d;
        } else {
            acc.x = fmaxf(acc.x + bx, 0.f); acc.y = fmaxf(acc.y + by, 0.f);
            acc.z = fmaxf(acc.z + bz, 0.f); acc.w = fmaxf(acc.w + bw, 0.f);
        }
        __half2* op = reinterpret_cast<__half2*>(&O[(long)row1 * FOUT + fx]);
        op[0] = __floats2half2_rn(acc.x, acc.y);
        op[1] = __floats2half2_rn(acc.z, acc.w);
    }
}

// ------------------------- Pool + MLP head (fused) --------------------------
// Final features fp16 in g_hA (stride 32). batch sorted -> binary search.

__global__ void k_pool_mlp(const int* __restrict__ batch, int n,
                           const float* __restrict__ Wh1, const float* __restrict__ bh1,
                           const float* __restrict__ Wh2, const float* __restrict__ bh2,
                           float* __restrict__ out) {
    int g = blockIdx.x;
    int lo = 0, hi = n;
    while (lo < hi) { int mid = (lo + hi) >> 1; if (batch[mid] < g) lo = mid + 1; else hi = mid; }
    int start = lo;
    hi = n;
    while (lo < hi) { int mid = (lo + hi) >> 1; if (batch[mid] < g + 1) lo = mid + 1; else hi = mid; }
    int end = lo;

    __shared__ float partial[4][32];
    __shared__ float gsum[32];
    int f = threadIdx.x & 31;
    int r = threadIdx.x >> 5;
    float acc = 0.f;
    for (int i = start + r; i < end; i += 4) acc += __half2float(g_hA[(long)i * 32 + f]);
    partial[r][f] = acc;
    __syncthreads();

    if (threadIdx.x < 32) {
        float s = partial[0][f] + partial[1][f] + partial[2][f] + partial[3][f];
        float cnt = (float)((end - start) > 0 ? (end - start) : 1);
        gsum[f] = s / cnt;
    }
    __syncthreads();

    if (threadIdx.x < 32) {
        int o = threadIdx.x;
        float h = bh1[o];
#pragma unroll
        for (int k = 0; k < 32; k++) h = fmaf(gsum[k], Wh1[k * 32 + o], h);
        h = fmaxf(h, 0.f);
        float y = h * Wh2[o];
#pragma unroll
        for (int off = 16; off; off >>= 1) y += __shfl_down_sync(0xffffffffu, y, off);
        if (o == 0) out[g] = y + bh2[0];
    }
}

// ------------------------------- Launcher ----------------------------------

extern "C" void kernel_launch(void* const* d_in, const int* in_sizes, int n_in,
                              void* d_out, int out_size) {
    const float* x     = (const float*)d_in[0];
    const int*   ei    = (const int*)d_in[1];
    const int*   batch = (const int*)d_in[2];
    const float* W1  = (const float*)d_in[3];
    const float* b1  = (const float*)d_in[4];
    const float* W2  = (const float*)d_in[5];
    const float* b2  = (const float*)d_in[6];
    const float* W3  = (const float*)d_in[7];
    const float* b3  = (const float*)d_in[8];
    const float* Wh1 = (const float*)d_in[9];
    const float* bh1 = (const float*)d_in[10];
    const float* Wh2 = (const float*)d_in[11];
    const float* bh2 = (const float*)d_in[12];
    float* out = (float*)d_out;

    int N = in_sizes[0] / 25;
    int E = in_sizes[1] / 2;
    const int* src = ei;
    const int* dst = ei + E;

    int nThreads = 256;
    int nBlkN = (N + nThreads - 1) / nThreads;
    int nBlkE16 = (E + nThreads * 16 - 1) / (nThreads * 16);
    int agg4Blocks = (N + 63) / 64;    // U4R=4: 8 nodes/warp, 8 warps/block
    int agg8Blocks = (N + 31) / 32;    // U4R=8: 4 nodes/warp, 8 warps/block

    // --- Clear counters ---
    void* p = nullptr;
    cudaGetSymbolAddress(&p, g_cnt);
    cudaMemsetAsync(p, 0, N * sizeof(int));

    // --- Bucket adjacency build (single edge pass) ---
    k_fill<<<nBlkE16, nThreads>>>(src, dst, E);
    k_dinv_pad<<<nBlkN, nThreads>>>(N);

    // --- Layer 1: prep -> aggregate (stride 32) -> 25->64 GEMM ---
    k_prep<<<((N + 1) * 16 + 255) / 256, 256>>>(x, N);        // x -> A (+sentinel)
    k_agg_g<4, 0, 0><<<agg4Blocks, 256>>>(nullptr, N);        // A -> B
    k_gemm_h<32, 25, 64, 1, 1><<<(N + 31) / 32, 256>>>(W1, b1, N);  // B -> A

    // --- Layer 2 ---
    k_gemm_h<64, 64, 64, 0, 0><<<(N + 31) / 32, 256>>>(W2, nullptr, N);  // A -> B (+sentinel@64)
    k_agg_g<8, 1, 1><<<agg8Blocks, 256>>>(b2, N);                        // B -> A

    // --- Layer 3 ---
    k_gemm_h<64, 64, 32, 0, 0><<<(N + 63) / 64, 256>>>(W3, nullptr, N);  // A -> B (+sentinel@32)
    k_agg_g<4, 1, 1><<<agg4Blocks, 256>>>(b3, N);                        // B -> A

    // --- Pool + MLP head ---
    k_pool_mlp<<<GMAX, 128>>>(batch, N, Wh1, bh1, Wh2, bh2, out);
}

// round 14
// speedup vs baseline: 1.0062x; 1.0062x over previous
#include <cuda_runtime.h>
#include <cuda_fp16.h>

// ---------------------------------------------------------------------------
// MutationAwareGNN R14: R12 measured-best aggregation restored — unified
// 4-lane-group shape (8 virtual rows/warp), F=64 via 2 half-row segments
// (32 gathers in flight per warp; concurrency beats wavefront efficiency on
// this workload — confirmed R10/R13). Guard-free 4-edge unroll, aligned int4
// col prefetch, pairwise HADD2 pre-add, fp32 accumulate. Fill: 16 edges/thr.
// Bucket adjacency + zero-row sentinels written by producers at their stride.
// ---------------------------------------------------------------------------

#define NMAX 100000
#define EMAX 3200000
#define GMAX 256
#define CAP  128          // bucket capacity (Poisson(32) degrees: safe)

__device__ int    g_cnt[NMAX];
__device__ int    g_cnte4[NMAX];             // padded count, multiple of 4
__device__ int    g_col[(NMAX + 1) * CAP];   // +1 spare bucket absorbs over-reads
__device__ float  g_dinv[NMAX];
__device__ __half g_hA[(NMAX + 1) * 64];     // row n = zero sentinel (per layout)
__device__ __half g_hB[(NMAX + 1) * 64];

// ---------------------------- Bucket fill ----------------------------------

__global__ void k_fill(const int* __restrict__ src, const int* __restrict__ dst, int E) {
    int e16 = (blockIdx.x * blockDim.x + threadIdx.x) * 16;
    if (e16 + 15 < E) {
        int4 s[4], d[4];
#pragma unroll
        for (int q = 0; q < 4; q++) {
            s[q] = *reinterpret_cast<const int4*>(&src[e16 + q * 4]);
            d[q] = *reinterpret_cast<const int4*>(&dst[e16 + q * 4]);
        }
#pragma unroll
        for (int q = 0; q < 4; q++) {
            int p0 = atomicAdd(&g_cnt[d[q].x], 1);
            int p1 = atomicAdd(&g_cnt[d[q].y], 1);
            int p2 = atomicAdd(&g_cnt[d[q].z], 1);
            int p3 = atomicAdd(&g_cnt[d[q].w], 1);
            if (p0 < CAP) g_col[d[q].x * CAP + p0] = s[q].x;
            if (p1 < CAP) g_col[d[q].y * CAP + p1] = s[q].y;
            if (p2 < CAP) g_col[d[q].z * CAP + p2] = s[q].z;
            if (p3 < CAP) g_col[d[q].w * CAP + p3] = s[q].w;
        }
    } else {
        for (int e = e16; e < E; e++) {
            int dd = dst[e];
            int p = atomicAdd(&g_cnt[dd], 1);
            if (p < CAP) g_col[dd * CAP + p] = src[e];
        }
    }
}

// dinv + pad buckets to multiple of 4 with sentinel index n (zero row).
__global__ void k_dinv_pad(int n) {
    int i = blockIdx.x * blockDim.x + threadIdx.x;
    if (i >= n) return;
    int c   = min(g_cnt[i], CAP);
    int ce4 = (c + 3) & ~3;
    for (int s = c; s < ce4; s++) g_col[i * CAP + s] = n;  // sentinel -> zero row
    g_cnte4[i] = ce4;
    g_dinv[i]  = rsqrtf((float)(c + 1));                   // +1 self-loop
}

// ------------------------------ Prep (layer 1) ------------------------------
// g_hA rows 0..n-1 = dinv_j * x_j (25 features padded to 32 fp16); row n = 0.

__global__ void k_prep(const float* __restrict__ x, int n) {
    int i = blockIdx.x * blockDim.x + threadIdx.x;   // half2 slot
    if (i >= (n + 1) * 16) return;
    int node = i >> 4, f2 = i & 15;
    float a = 0.f, b = 0.f;
    if (node < n) {
        float d = g_dinv[node];
        int f = f2 * 2;
        a = (f     < 25) ? d * __ldg(&x[node * 25 + f])     : 0.f;
        b = (f + 1 < 25) ? d * __ldg(&x[node * 25 + f + 1]) : 0.f;
    }
    reinterpret_cast<__half2*>(g_hA)[i] = __floats2half2_rn(a, b);
}

// ----------------------------- Aggregation ---------------------------------
// Unified shape: 4-lane groups, 8 virtual rows per warp. A virtual row is
// (node, seg) with seg in [0, SEGS); SEGS = F/32. 4-edge unrolled guard-free
// loop: buckets padded to multiple of 4, sentinel row n is zero, col indices
// prefetched as one int4 (bucket base 128-aligned, step 4).

template <int SEGS, int RELU, int SRC>
__global__ void k_agg_g(const float* __restrict__ bias, int n) {
    constexpr int ST = SEGS * 4;      // uint4 per full row (F/8)
    int wid  = (blockIdx.x * blockDim.x + threadIdx.x) >> 5;
    int lane = threadIdx.x & 31;
    int grp = lane >> 2;              // 0..7 virtual rows per warp
    int sub = lane & 3;               // uint4 chunk within segment
    int vrow = wid * 8 + grp;
    int node = (SEGS == 1) ? vrow : (vrow >> 1);
    int seg  = (SEGS == 1) ? 0    : (vrow & 1);
    bool valid = node < n;
    int nd = valid ? node : n;        // sentinel row safe to gather
    int so = seg * 4 + sub;           // uint4 offset within row

    const uint4* base = reinterpret_cast<const uint4*>(SRC ? g_hB : g_hA);
    __half*      db   = SRC ? g_hA : g_hB;

    // self-loop term
    float acc[8];
    {
        uint4 v = base[nd * ST + so];
        float2 f0 = __half22float2(*reinterpret_cast<__half2*>(&v.x));
        float2 f1 = __half22float2(*reinterpret_cast<__half2*>(&v.y));
        float2 f2 = __half22float2(*reinterpret_cast<__half2*>(&v.z));
        float2 f3 = __half22float2(*reinterpret_cast<__half2*>(&v.w));
        acc[0] = f0.x; acc[1] = f0.y; acc[2] = f1.x; acc[3] = f1.y;
        acc[4] = f2.x; acc[5] = f2.y; acc[6] = f3.x; acc[7] = f3.y;
    }

    int e    = node * CAP;
    int endv = e + (valid ? g_cnte4[node] : 0);
    int4 jj = *reinterpret_cast<const int4*>(&g_col[e]);
    while (e < endv) {
        uint4 v0 = base[jj.x * ST + so];
        uint4 v1 = base[jj.y * ST + so];
        uint4 v2 = base[jj.z * ST + so];
        uint4 v3 = base[jj.w * ST + so];
        e += 4;
        jj = *reinterpret_cast<const int4*>(&g_col[e]);   // prefetch (spare bucket)
        // pairwise fp16 pre-add (depth 1), then fp32 accumulate
        __half2 a0 = __hadd2(*reinterpret_cast<__half2*>(&v0.x), *reinterpret_cast<__half2*>(&v1.x));
        __half2 a1 = __hadd2(*reinterpret_cast<__half2*>(&v0.y), *reinterpret_cast<__half2*>(&v1.y));
        __half2 a2 = __hadd2(*reinterpret_cast<__half2*>(&v0.z), *reinterpret_cast<__half2*>(&v1.z));
        __half2 a3 = __hadd2(*reinterpret_cast<__half2*>(&v0.w), *reinterpret_cast<__half2*>(&v1.w));
        __half2 b0 = __hadd2(*reinterpret_cast<__half2*>(&v2.x), *reinterpret_cast<__half2*>(&v3.x));
        __half2 b1 = __hadd2(*reinterpret_cast<__half2*>(&v2.y), *reinterpret_cast<__half2*>(&v3.y));
        __half2 b2 = __hadd2(*reinterpret_cast<__half2*>(&v2.z), *reinterpret_cast<__half2*>(&v3.z));
        __half2 b3 = __hadd2(*reinterpret_cast<__half2*>(&v2.w), *reinterpret_cast<__half2*>(&v3.w));
        float2 fa0 = __half22float2(a0), fa1 = __half22float2(a1);
        float2 fa2 = __half22float2(a2), fa3 = __half22float2(a3);
        float2 fb0 = __half22float2(b0), fb1 = __half22float2(b1);
        float2 fb2 = __half22float2(b2), fb3 = __half22float2(b3);
        acc[0] += fa0.x + fb0.x; acc[1] += fa0.y + fb0.y;
        acc[2] += fa1.x + fb1.x; acc[3] += fa1.y + fb1.y;
        acc[4] += fa2.x + fb2.x; acc[5] += fa2.y + fb2.y;
        acc[6] += fa3.x + fb3.x; acc[7] += fa3.y + fb3.y;
    }

    if (valid) {
        float d = g_dinv[node];
        __half out[8];
#pragma unroll
        for (int k = 0; k < 8; k++) {
            float r;
            if (RELU) r = fmaxf(fmaf(acc[k], d, __ldg(&bias[seg * 32 + sub * 8 + k])), 0.f);
            else      r = acc[k] * d;
            out[k] = __float2half_rn(r);
        }
        reinterpret_cast<uint4*>(db)[node * ST + so] = *reinterpret_cast<uint4*>(out);
    }
}

// ------------------------------- Dense GEMM --------------------------------
// 2 rows per thread. Block 0 writes the zero sentinel row n at the OUTPUT
// stride, so a following agg reading O sees zeros at index n.

template <int FINP, int FINW, int FOUT, int EPI, int SRC>
__global__ void k_gemm_h(const float* __restrict__ W, const float* __restrict__ bias, int n) {
    __shared__ float Wsh[FINP * FOUT];
    for (int i = threadIdx.x; i < FINP * FOUT; i += blockDim.x)
        Wsh[i] = (i < FINW * FOUT) ? W[i] : 0.f;
    __syncthreads();

    const __half* X = SRC ? g_hB : g_hA;
    __half*       O = SRC ? g_hA : g_hB;

    if (blockIdx.x == 0 && threadIdx.x < FOUT / 8) {   // zero sentinel row n
        reinterpret_cast<uint4*>(O)[(long)n * (FOUT / 8) + threadIdx.x] =
            make_uint4(0u, 0u, 0u, 0u);
    }

    constexpr int TPR  = FOUT / 4;
    constexpr int RPB  = 256 / TPR;
    constexpr int RPB2 = RPB * 2;
    int slot = (int)(threadIdx.x / TPR);
    int row0 = blockIdx.x * RPB2 + slot;
    int row1 = row0 + RPB;
    int fx = (threadIdx.x % TPR) * 4;
    bool v0 = row0 < n, v1 = row1 < n;
    if (!v0) return;

    const uint4* xr0 = reinterpret_cast<const uint4*>(X + (long)row0 * FINP);
    const uint4* xr1 = reinterpret_cast<const uint4*>(X + (long)(v1 ? row1 : row0) * FINP);
    float4 a0 = make_float4(0.f, 0.f, 0.f, 0.f);
    float4 a1 = make_float4(0.f, 0.f, 0.f, 0.f);
#pragma unroll
    for (int q = 0; q < FINP / 8; q++) {
        uint4 p0 = __ldg(&xr0[q]);
        uint4 p1 = __ldg(&xr1[q]);
        const unsigned* u0 = &p0.x;
        const unsigned* u1 = &p1.x;
#pragma unroll
        for (int t = 0; t < 4; t++) {
            float2 f0 = __half22float2(*reinterpret_cast<const __half2*>(&u0[t]));
            float2 f1 = __half22float2(*reinterpret_cast<const __half2*>(&u1[t]));
            int k = q * 8 + t * 2;
            float4 w0 = *reinterpret_cast<const float4*>(&Wsh[k * FOUT + fx]);
            float4 w1 = *reinterpret_cast<const float4*>(&Wsh[(k + 1) * FOUT + fx]);
            a0.x = fmaf(f0.x, w0.x, fmaf(f0.y, w1.x, a0.x));
            a0.y = fmaf(f0.x, w0.y, fmaf(f0.y, w1.y, a0.y));
            a0.z = fmaf(f0.x, w0.z, fmaf(f0.y, w1.z, a0.z));
            a0.w = fmaf(f0.x, w0.w, fmaf(f0.y, w1.w, a0.w));
            a1.x = fmaf(f1.x, w0.x, fmaf(f1.y, w1.x, a1.x));
            a1.y = fmaf(f1.x, w0.y, fmaf(f1.y, w1.y, a1.y));
            a1.z = fmaf(f1.x, w0.z, fmaf(f1.y, w1.z, a1.z));
            a1.w = fmaf(f1.x, w0.w, fmaf(f1.y, w1.w, a1.w));
        }
    }

    float bx = 0.f, by = 0.f, bz = 0.f, bw = 0.f;
    if (EPI == 1) {
        bx = __ldg(&bias[fx + 0]); by = __ldg(&bias[fx + 1]);
        bz = __ldg(&bias[fx + 2]); bw = __ldg(&bias[fx + 3]);
    }
    {
        float4 acc = a0;
        if (EPI == 0) {
            float d = g_dinv[row0];
            acc.x *= d; acc.y *= d; acc.z *= d; acc.w *= d;
        } else {
            acc.x = fmaxf(acc.x + bx, 0.f); acc.y = fmaxf(acc.y + by, 0.f);
            acc.z = fmaxf(acc.z + bz, 0.f); acc.w = fmaxf(acc.w + bw, 0.f);
        }
        __half2* op = reinterpret_cast<__half2*>(&O[(long)row0 * FOUT + fx]);
        op[0] = __floats2half2_rn(acc.x, acc.y);
        op[1] = __floats2half2_rn(acc.z, acc.w);
    }
    if (v1) {
        float4 acc = a1;
        if (EPI == 0) {
            float d = g_dinv[row1];
            acc.x *= d; acc.y *= d; acc.z *= d; acc.w *= d;
        } else {
            acc.x = fmaxf(acc.x + bx, 0.f); acc.y = fmaxf(acc.y + by, 0.f);
            acc.z = fmaxf(acc.z + bz, 0.f); acc.w = fmaxf(acc.w + bw, 0.f);
        }
        __half2* op = reinterpret_cast<__half2*>(&O[(long)row1 * FOUT + fx]);
        op[0] = __floats2half2_rn(acc.x, acc.y);
        op[1] = __floats2half2_rn(acc.z, acc.w);
    }
}

// ------------------------- Pool + MLP head (fused) --------------------------
// Final features fp16 in g_hA (stride 32). batch sorted -> binary search.

__global__ void k_pool_mlp(const int* __restrict__ batch, int n,
                           const float* __restrict__ Wh1, const float* __restrict__ bh1,
                           const float* __restrict__ Wh2, const float* __restrict__ bh2,
                           float* __restrict__ out) {
    int g = blockIdx.x;
    int lo = 0, hi = n;
    while (lo < hi) { int mid = (lo + hi) >> 1; if (batch[mid] < g) lo = mid + 1; else hi = mid; }
    int start = lo;
    hi = n;
    while (lo < hi) { int mid = (lo + hi) >> 1; if (batch[mid] < g + 1) lo = mid + 1; else hi = mid; }
    int end = lo;

    __shared__ float partial[4][32];
    __shared__ float gsum[32];
    int f = threadIdx.x & 31;
    int r = threadIdx.x >> 5;
    float acc = 0.f;
    for (int i = start + r; i < end; i += 4) acc += __half2float(g_hA[(long)i * 32 + f]);
    partial[r][f] = acc;
    __syncthreads();

    if (threadIdx.x < 32) {
        float s = partial[0][f] + partial[1][f] + partial[2][f] + partial[3][f];
        float cnt = (float)((end - start) > 0 ? (end - start) : 1);
        gsum[f] = s / cnt;
    }
    __syncthreads();

    if (threadIdx.x < 32) {
        int o = threadIdx.x;
        float h = bh1[o];
#pragma unroll
        for (int k = 0; k < 32; k++) h = fmaf(gsum[k], Wh1[k * 32 + o], h);
        h = fmaxf(h, 0.f);
        float y = h * Wh2[o];
#pragma unroll
        for (int off = 16; off; off >>= 1) y += __shfl_down_sync(0xffffffffu, y, off);
        if (o == 0) out[g] = y + bh2[0];
    }
}

// ------------------------------- Launcher ----------------------------------

extern "C" void kernel_launch(void* const* d_in, const int* in_sizes, int n_in,
                              void* d_out, int out_size) {
    const float* x     = (const float*)d_in[0];
    const int*   ei    = (const int*)d_in[1];
    const int*   batch = (const int*)d_in[2];
    const float* W1  = (const float*)d_in[3];
    const float* b1  = (const float*)d_in[4];
    const float* W2  = (const float*)d_in[5];
    const float* b2  = (const float*)d_in[6];
    const float* W3  = (const float*)d_in[7];
    const float* b3  = (const float*)d_in[8];
    const float* Wh1 = (const float*)d_in[9];
    const float* bh1 = (const float*)d_in[10];
    const float* Wh2 = (const float*)d_in[11];
    const float* bh2 = (const float*)d_in[12];
    float* out = (float*)d_out;

    int N = in_sizes[0] / 25;
    int E = in_sizes[1] / 2;
    const int* src = ei;
    const int* dst = ei + E;

    int nThreads = 256;
    int nBlkN = (N + nThreads - 1) / nThreads;
    int nBlkE16 = (E + nThreads * 16 - 1) / (nThreads * 16);
    int agg1Blocks = (N + 63) / 64;          // SEGS=1: 8 nodes/warp
    int agg2Blocks = (2 * N + 63) / 64;      // SEGS=2: 2N virtual rows

    // --- Clear counters ---
    void* p = nullptr;
    cudaGetSymbolAddress(&p, g_cnt);
    cudaMemsetAsync(p, 0, N * sizeof(int));

    // --- Bucket adjacency build (single edge pass) ---
    k_fill<<<nBlkE16, nThreads>>>(src, dst, E);
    k_dinv_pad<<<nBlkN, nThreads>>>(N);

    // --- Layer 1: prep -> aggregate (stride 32) -> 25->64 GEMM ---
    k_prep<<<((N + 1) * 16 + 255) / 256, 256>>>(x, N);        // x -> A (+sentinel)
    k_agg_g<1, 0, 0><<<agg1Blocks, 256>>>(nullptr, N);        // A -> B
    k_gemm_h<32, 25, 64, 1, 1><<<(N + 31) / 32, 256>>>(W1, b1, N);  // B -> A

    // --- Layer 2 ---
    k_gemm_h<64, 64, 64, 0, 0><<<(N + 31) / 32, 256>>>(W2, nullptr, N);  // A -> B (+sentinel@64)
    k_agg_g<2, 1, 1><<<agg2Blocks, 256>>>(b2, N);                        // B -> A

    // --- Layer 3 ---
    k_gemm_h<64, 64, 32, 0, 0><<<(N + 63) / 64, 256>>>(W3, nullptr, N);  // A -> B (+sentinel@32)
    k_agg_g<1, 1, 1><<<agg1Blocks, 256>>>(b3, N);                        // B -> A

    // --- Pool + MLP head ---
    k_pool_mlp<<<GMAX, 128>>>(batch, N, Wh1, bh1, Wh2, bh2, out);
}

// round 15
// speedup vs baseline: 1.0189x; 1.0126x over previous
#include <cuda_runtime.h>
#include <cuda_fp16.h>

// ---------------------------------------------------------------------------
// MutationAwareGNN R15: R12 measured-best config restored (fill = 8 edges/thr;
// unified 4-lane-group aggs, F=64 via 2 half-row segments = 32 gathers in
// flight/warp; guard-free 4-edge unroll; HADD2 pre-add; fp32 accumulate) with
// dinv+pad merged into k_prep (one fewer launch). Bucket adjacency +
// zero-row sentinels written by each producer at its own stride.
// ---------------------------------------------------------------------------

#define NMAX 100000
#define EMAX 3200000
#define GMAX 256
#define CAP  128          // bucket capacity (Poisson(32) degrees: safe)

__device__ int    g_cnt[NMAX];
__device__ int    g_cnte4[NMAX];             // padded count, multiple of 4
__device__ int    g_col[(NMAX + 1) * CAP];   // +1 spare bucket absorbs over-reads
__device__ float  g_dinv[NMAX];
__device__ __half g_hA[(NMAX + 1) * 64];     // row n = zero sentinel (per layout)
__device__ __half g_hB[(NMAX + 1) * 64];

// ---------------------------- Bucket fill (8 edges/thread) ------------------

__global__ void k_fill(const int* __restrict__ src, const int* __restrict__ dst, int E) {
    int e8 = (blockIdx.x * blockDim.x + threadIdx.x) * 8;
    if (e8 + 7 < E) {
        int4 s0 = *reinterpret_cast<const int4*>(&src[e8]);
        int4 s1 = *reinterpret_cast<const int4*>(&src[e8 + 4]);
        int4 d0 = *reinterpret_cast<const int4*>(&dst[e8]);
        int4 d1 = *reinterpret_cast<const int4*>(&dst[e8 + 4]);
        int p0 = atomicAdd(&g_cnt[d0.x], 1);
        int p1 = atomicAdd(&g_cnt[d0.y], 1);
        int p2 = atomicAdd(&g_cnt[d0.z], 1);
        int p3 = atomicAdd(&g_cnt[d0.w], 1);
        int p4 = atomicAdd(&g_cnt[d1.x], 1);
        int p5 = atomicAdd(&g_cnt[d1.y], 1);
        int p6 = atomicAdd(&g_cnt[d1.z], 1);
        int p7 = atomicAdd(&g_cnt[d1.w], 1);
        if (p0 < CAP) g_col[d0.x * CAP + p0] = s0.x;
        if (p1 < CAP) g_col[d0.y * CAP + p1] = s0.y;
        if (p2 < CAP) g_col[d0.z * CAP + p2] = s0.z;
        if (p3 < CAP) g_col[d0.w * CAP + p3] = s0.w;
        if (p4 < CAP) g_col[d1.x * CAP + p4] = s1.x;
        if (p5 < CAP) g_col[d1.y * CAP + p5] = s1.y;
        if (p6 < CAP) g_col[d1.z * CAP + p6] = s1.z;
        if (p7 < CAP) g_col[d1.w * CAP + p7] = s1.w;
    } else {
        for (int e = e8; e < E; e++) {
            int d = dst[e];
            int p = atomicAdd(&g_cnt[d], 1);
            if (p < CAP) g_col[d * CAP + p] = src[e];
        }
    }
}

// -------------------- Prep (layer 1) + dinv + bucket pad --------------------
// Per half2 slot: g_hA rows 0..n-1 = dinv_j * x_j (25 features padded to 32
// fp16); row n = zero sentinel. The f2==0 lane of each node also writes
// g_dinv/g_cnte4 and pads the bucket to a multiple of 4 with sentinel n.

__global__ void k_prep(const float* __restrict__ x, int n) {
    int i = blockIdx.x * blockDim.x + threadIdx.x;   // half2 slot
    if (i >= (n + 1) * 16) return;
    int node = i >> 4, f2 = i & 15;
    float a = 0.f, b = 0.f;
    if (node < n) {
        int c = min(g_cnt[node], CAP);
        float d = rsqrtf((float)(c + 1));            // +1 self-loop
        if (f2 == 0) {
            int ce4 = (c + 3) & ~3;
            for (int s = c; s < ce4; s++) g_col[node * CAP + s] = n;  // sentinel
            g_cnte4[node] = ce4;
            g_dinv[node]  = d;
        }
        int f = f2 * 2;
        a = (f     < 25) ? d * __ldg(&x[node * 25 + f])     : 0.f;
        b = (f + 1 < 25) ? d * __ldg(&x[node * 25 + f + 1]) : 0.f;
    }
    reinterpret_cast<__half2*>(g_hA)[i] = __floats2half2_rn(a, b);
}

// ----------------------------- Aggregation ---------------------------------
// Unified shape: 4-lane groups, 8 virtual rows per warp. A virtual row is
// (node, seg) with seg in [0, SEGS); SEGS = F/32. 4-edge unrolled guard-free
// loop: buckets padded to multiple of 4, sentinel row n is zero, col indices
// prefetched as one int4 (bucket base 128-aligned, step 4).

template <int SEGS, int RELU, int SRC>
__global__ void k_agg_g(const float* __restrict__ bias, int n) {
    constexpr int ST = SEGS * 4;      // uint4 per full row (F/8)
    int wid  = (blockIdx.x * blockDim.x + threadIdx.x) >> 5;
    int lane = threadIdx.x & 31;
    int grp = lane >> 2;              // 0..7 virtual rows per warp
    int sub = lane & 3;               // uint4 chunk within segment
    int vrow = wid * 8 + grp;
    int node = (SEGS == 1) ? vrow : (vrow >> 1);
    int seg  = (SEGS == 1) ? 0    : (vrow & 1);
    bool valid = node < n;
    int nd = valid ? node : n;        // sentinel row safe to gather
    int so = seg * 4 + sub;           // uint4 offset within row

    const uint4* base = reinterpret_cast<const uint4*>(SRC ? g_hB : g_hA);
    __half*      db   = SRC ? g_hA : g_hB;

    // self-loop term
    float acc[8];
    {
        uint4 v = base[nd * ST + so];
        float2 f0 = __half22float2(*reinterpret_cast<__half2*>(&v.x));
        float2 f1 = __half22float2(*reinterpret_cast<__half2*>(&v.y));
        float2 f2 = __half22float2(*reinterpret_cast<__half2*>(&v.z));
        float2 f3 = __half22float2(*reinterpret_cast<__half2*>(&v.w));
        acc[0] = f0.x; acc[1] = f0.y; acc[2] = f1.x; acc[3] = f1.y;
        acc[4] = f2.x; acc[5] = f2.y; acc[6] = f3.x; acc[7] = f3.y;
    }

    int e    = node * CAP;
    int endv = e + (valid ? g_cnte4[node] : 0);
    int4 jj = *reinterpret_cast<const int4*>(&g_col[e]);
    while (e < endv) {
        uint4 v0 = base[jj.x * ST + so];
        uint4 v1 = base[jj.y * ST + so];
        uint4 v2 = base[jj.z * ST + so];
        uint4 v3 = base[jj.w * ST + so];
        e += 4;
        jj = *reinterpret_cast<const int4*>(&g_col[e]);   // prefetch (spare bucket)
        // pairwise fp16 pre-add (depth 1), then fp32 accumulate
        __half2 a0 = __hadd2(*reinterpret_cast<__half2*>(&v0.x), *reinterpret_cast<__half2*>(&v1.x));
        __half2 a1 = __hadd2(*reinterpret_cast<__half2*>(&v0.y), *reinterpret_cast<__half2*>(&v1.y));
        __half2 a2 = __hadd2(*reinterpret_cast<__half2*>(&v0.z), *reinterpret_cast<__half2*>(&v1.z));
        __half2 a3 = __hadd2(*reinterpret_cast<__half2*>(&v0.w), *reinterpret_cast<__half2*>(&v1.w));
        __half2 b0 = __hadd2(*reinterpret_cast<__half2*>(&v2.x), *reinterpret_cast<__half2*>(&v3.x));
        __half2 b1 = __hadd2(*reinterpret_cast<__half2*>(&v2.y), *reinterpret_cast<__half2*>(&v3.y));
        __half2 b2 = __hadd2(*reinterpret_cast<__half2*>(&v2.z), *reinterpret_cast<__half2*>(&v3.z));
        __half2 b3 = __hadd2(*reinterpret_cast<__half2*>(&v2.w), *reinterpret_cast<__half2*>(&v3.w));
        float2 fa0 = __half22float2(a0), fa1 = __half22float2(a1);
        float2 fa2 = __half22float2(a2), fa3 = __half22float2(a3);
        float2 fb0 = __half22float2(b0), fb1 = __half22float2(b1);
        float2 fb2 = __half22float2(b2), fb3 = __half22float2(b3);
        acc[0] += fa0.x + fb0.x; acc[1] += fa0.y + fb0.y;
        acc[2] += fa1.x + fb1.x; acc[3] += fa1.y + fb1.y;
        acc[4] += fa2.x + fb2.x; acc[5] += fa2.y + fb2.y;
        acc[6] += fa3.x + fb3.x; acc[7] += fa3.y + fb3.y;
    }

    if (valid) {
        float d = g_dinv[node];
        __half out[8];
#pragma unroll
        for (int k = 0; k < 8; k++) {
            float r;
            if (RELU) r = fmaxf(fmaf(acc[k], d, __ldg(&bias[seg * 32 + sub * 8 + k])), 0.f);
            else      r = acc[k] * d;
            out[k] = __float2half_rn(r);
        }
        reinterpret_cast<uint4*>(db)[node * ST + so] = *reinterpret_cast<uint4*>(out);
    }
}

// ------------------------------- Dense GEMM --------------------------------
// 2 rows per thread. Block 0 writes the zero sentinel row n at the OUTPUT
// stride, so a following agg reading O sees zeros at index n.

template <int FINP, int FINW, int FOUT, int EPI, int SRC>
__global__ void k_gemm_h(const float* __restrict__ W, const float* __restrict__ bias, int n) {
    __shared__ float Wsh[FINP * FOUT];
    for (int i = threadIdx.x; i < FINP * FOUT; i += blockDim.x)
        Wsh[i] = (i < FINW * FOUT) ? W[i] : 0.f;
    __syncthreads();

    const __half* X = SRC ? g_hB : g_hA;
    __half*       O = SRC ? g_hA : g_hB;

    if (blockIdx.x == 0 && threadIdx.x < FOUT / 8) {   // zero sentinel row n
        reinterpret_cast<uint4*>(O)[(long)n * (FOUT / 8) + threadIdx.x] =
            make_uint4(0u, 0u, 0u, 0u);
    }

    constexpr int TPR  = FOUT / 4;
    constexpr int RPB  = 256 / TPR;
    constexpr int RPB2 = RPB * 2;
    int slot = (int)(threadIdx.x / TPR);
    int row0 = blockIdx.x * RPB2 + slot;
    int row1 = row0 + RPB;
    int fx = (threadIdx.x % TPR) * 4;
    bool v0 = row0 < n, v1 = row1 < n;
    if (!v0) return;

    const uint4* xr0 = reinterpret_cast<const uint4*>(X + (long)row0 * FINP);
    const uint4* xr1 = reinterpret_cast<const uint4*>(X + (long)(v1 ? row1 : row0) * FINP);
    float4 a0 = make_float4(0.f, 0.f, 0.f, 0.f);
    float4 a1 = make_float4(0.f, 0.f, 0.f, 0.f);
#pragma unroll
    for (int q = 0; q < FINP / 8; q++) {
        uint4 p0 = __ldg(&xr0[q]);
        uint4 p1 = __ldg(&xr1[q]);
        const unsigned* u0 = &p0.x;
        const unsigned* u1 = &p1.x;
#pragma unroll
        for (int t = 0; t < 4; t++) {
            float2 f0 = __half22float2(*reinterpret_cast<const __half2*>(&u0[t]));
            float2 f1 = __half22float2(*reinterpret_cast<const __half2*>(&u1[t]));
            int k = q * 8 + t * 2;
            float4 w0 = *reinterpret_cast<const float4*>(&Wsh[k * FOUT + fx]);
            float4 w1 = *reinterpret_cast<const float4*>(&Wsh[(k + 1) * FOUT + fx]);
            a0.x = fmaf(f0.x, w0.x, fmaf(f0.y, w1.x, a0.x));
            a0.y = fmaf(f0.x, w0.y, fmaf(f0.y, w1.y, a0.y));
            a0.z = fmaf(f0.x, w0.z, fmaf(f0.y, w1.z, a0.z));
            a0.w = fmaf(f0.x, w0.w, fmaf(f0.y, w1.w, a0.w));
            a1.x = fmaf(f1.x, w0.x, fmaf(f1.y, w1.x, a1.x));
            a1.y = fmaf(f1.x, w0.y, fmaf(f1.y, w1.y, a1.y));
            a1.z = fmaf(f1.x, w0.z, fmaf(f1.y, w1.z, a1.z));
            a1.w = fmaf(f1.x, w0.w, fmaf(f1.y, w1.w, a1.w));
        }
    }

    float bx = 0.f, by = 0.f, bz = 0.f, bw = 0.f;
    if (EPI == 1) {
        bx = __ldg(&bias[fx + 0]); by = __ldg(&bias[fx + 1]);
        bz = __ldg(&bias[fx + 2]); bw = __ldg(&bias[fx + 3]);
    }
    {
        float4 acc = a0;
        if (EPI == 0) {
            float d = g_dinv[row0];
            acc.x *= d; acc.y *= d; acc.z *= d; acc.w *= d;
        } else {
            acc.x = fmaxf(acc.x + bx, 0.f); acc.y = fmaxf(acc.y + by, 0.f);
            acc.z = fmaxf(acc.z + bz, 0.f); acc.w = fmaxf(acc.w + bw, 0.f);
        }
        __half2* op = reinterpret_cast<__half2*>(&O[(long)row0 * FOUT + fx]);
        op[0] = __floats2half2_rn(acc.x, acc.y);
        op[1] = __floats2half2_rn(acc.z, acc.w);
    }
    if (v1) {
        float4 acc = a1;
        if (EPI == 0) {
            float d = g_dinv[row1];
            acc.x *= d; acc.y *= d; acc.z *= d; acc.w *= d;
        } else {
            acc.x = fmaxf(acc.x + bx, 0.f); acc.y = fmaxf(acc.y + by, 0.f);
            acc.z = fmaxf(acc.z + bz, 0.f); acc.w = fmaxf(acc.w + bw, 0.f);
        }
        __half2* op = reinterpret_cast<__half2*>(&O[(long)row1 * FOUT + fx]);
        op[0] = __floats2half2_rn(acc.x, acc.y);
        op[1] = __floats2half2_rn(acc.z, acc.w);
    }
}

// ------------------------- Pool + MLP head (fused) --------------------------
// Final features fp16 in g_hA (stride 32). batch sorted -> binary search.

__global__ void k_pool_mlp(const int* __restrict__ batch, int n,
                           const float* __restrict__ Wh1, const float* __restrict__ bh1,
                           const float* __restrict__ Wh2, const float* __restrict__ bh2,
                           float* __restrict__ out) {
    int g = blockIdx.x;
    int lo = 0, hi = n;
    while (lo < hi) { int mid = (lo + hi) >> 1; if (batch[mid] < g) lo = mid + 1; else hi = mid; }
    int start = lo;
    hi = n;
    while (lo < hi) { int mid = (lo + hi) >> 1; if (batch[mid] < g + 1) lo = mid + 1; else hi = mid; }
    int end = lo;

    __shared__ float partial[4][32];
    __shared__ float gsum[32];
    int f = threadIdx.x & 31;
    int r = threadIdx.x >> 5;
    float acc = 0.f;
    for (int i = start + r; i < end; i += 4) acc += __half2float(g_hA[(long)i * 32 + f]);
    partial[r][f] = acc;
    __syncthreads();

    if (threadIdx.x < 32) {
        float s = partial[0][f] + partial[1][f] + partial[2][f] + partial[3][f];
        float cnt = (float)((end - start) > 0 ? (end - start) : 1);
        gsum[f] = s / cnt;
    }
    __syncthreads();

    if (threadIdx.x < 32) {
        int o = threadIdx.x;
        float h = bh1[o];
#pragma unroll
        for (int k = 0; k < 32; k++) h = fmaf(gsum[k], Wh1[k * 32 + o], h);
        h = fmaxf(h, 0.f);
        float y = h * Wh2[o];
#pragma unroll
        for (int off = 16; off; off >>= 1) y += __shfl_down_sync(0xffffffffu, y, off);
        if (o == 0) out[g] = y + bh2[0];
    }
}

// ------------------------------- Launcher ----------------------------------

extern "C" void kernel_launch(void* const* d_in, const int* in_sizes, int n_in,
                              void* d_out, int out_size) {
    const float* x     = (const float*)d_in[0];
    const int*   ei    = (const int*)d_in[1];
    const int*   batch = (const int*)d_in[2];
    const float* W1  = (const float*)d_in[3];
    const float* b1  = (const float*)d_in[4];
    const float* W2  = (const float*)d_in[5];
    const float* b2  = (const float*)d_in[6];
    const float* W3  = (const float*)d_in[7];
    const float* b3  = (const float*)d_in[8];
    const float* Wh1 = (const float*)d_in[9];
    const float* bh1 = (const float*)d_in[10];
    const float* Wh2 = (const float*)d_in[11];
    const float* bh2 = (const float*)d_in[12];
    float* out = (float*)d_out;

    int N = in_sizes[0] / 25;
    int E = in_sizes[1] / 2;
    const int* src = ei;
    const int* dst = ei + E;

    int nThreads = 256;
    int nBlkE8 = (E + nThreads * 8 - 1) / (nThreads * 8);
    int agg1Blocks = (N + 63) / 64;          // SEGS=1: 8 nodes/warp
    int agg2Blocks = (2 * N + 63) / 64;      // SEGS=2: 2N virtual rows

    // --- Clear counters ---
    void* p = nullptr;
    cudaGetSymbolAddress(&p, g_cnt);
    cudaMemsetAsync(p, 0, N * sizeof(int));

    // --- Bucket adjacency build (single edge pass) ---
    k_fill<<<nBlkE8, nThreads>>>(src, dst, E);

    // --- Layer 1: prep (+dinv+pad) -> aggregate -> 25->64 GEMM ---
    k_prep<<<((N + 1) * 16 + 255) / 256, 256>>>(x, N);        // x -> A (+sentinel)
    k_agg_g<1, 0, 0><<<agg1Blocks, 256>>>(nullptr, N);        // A -> B
    k_gemm_h<32, 25, 64, 1, 1><<<(N + 31) / 32, 256>>>(W1, b1, N);  // B -> A

    // --- Layer 2 ---
    k_gemm_h<64, 64, 64, 0, 0><<<(N + 31) / 32, 256>>>(W2, nullptr, N);  // A -> B (+sentinel@64)
    k_agg_g<2, 1, 1><<<agg2Blocks, 256>>>(b2, N);                        // B -> A

    // --- Layer 3 ---
    k_gemm_h<64, 64, 32, 0, 0><<<(N + 63) / 64, 256>>>(W3, nullptr, N);  // A -> B (+sentinel@32)
    k_agg_g<1, 1, 1><<<agg1Blocks, 256>>>(b3, N);                        // B -> A

    // --- Pool + MLP head ---
    k_pool_mlp<<<GMAX, 128>>>(batch, N, Wh1, bh1, Wh2, bh2, out);
}

// round 16
// speedup vs baseline: 1.0889x; 1.0687x over previous
#include <cuda_runtime.h>
#include <cuda_fp16.h>

// ---------------------------------------------------------------------------
// MutationAwareGNN R16: GEMMs widened to 4 rows/thread (halves LDS-per-FMA —
// R15 ncu showed gemm L1=72%, LDS-bound). Aggregation unchanged at measured
// best: unified 4-lane-group shape, F=64 via 2 half-row segments, guard-free
// 4-edge unroll, HADD2 pre-add, fp32 accumulate. Fill 8 edges/thread; dinv+
// pad merged into prep; bucket adjacency + zero-row sentinels.
// ---------------------------------------------------------------------------

#define NMAX 100000
#define EMAX 3200000
#define GMAX 256
#define CAP  128          // bucket capacity (Poisson(32) degrees: safe)

__device__ int    g_cnt[NMAX];
__device__ int    g_cnte4[NMAX];             // padded count, multiple of 4
__device__ int    g_col[(NMAX + 1) * CAP];   // +1 spare bucket absorbs over-reads
__device__ float  g_dinv[NMAX];
__device__ __half g_hA[(NMAX + 1) * 64];     // row n = zero sentinel (per layout)
__device__ __half g_hB[(NMAX + 1) * 64];

// ---------------------------- Bucket fill (8 edges/thread) ------------------

__global__ void k_fill(const int* __restrict__ src, const int* __restrict__ dst, int E) {
    int e8 = (blockIdx.x * blockDim.x + threadIdx.x) * 8;
    if (e8 + 7 < E) {
        int4 s0 = *reinterpret_cast<const int4*>(&src[e8]);
        int4 s1 = *reinterpret_cast<const int4*>(&src[e8 + 4]);
        int4 d0 = *reinterpret_cast<const int4*>(&dst[e8]);
        int4 d1 = *reinterpret_cast<const int4*>(&dst[e8 + 4]);
        int p0 = atomicAdd(&g_cnt[d0.x], 1);
        int p1 = atomicAdd(&g_cnt[d0.y], 1);
        int p2 = atomicAdd(&g_cnt[d0.z], 1);
        int p3 = atomicAdd(&g_cnt[d0.w], 1);
        int p4 = atomicAdd(&g_cnt[d1.x], 1);
        int p5 = atomicAdd(&g_cnt[d1.y], 1);
        int p6 = atomicAdd(&g_cnt[d1.z], 1);
        int p7 = atomicAdd(&g_cnt[d1.w], 1);
        if (p0 < CAP) g_col[d0.x * CAP + p0] = s0.x;
        if (p1 < CAP) g_col[d0.y * CAP + p1] = s0.y;
        if (p2 < CAP) g_col[d0.z * CAP + p2] = s0.z;
        if (p3 < CAP) g_col[d0.w * CAP + p3] = s0.w;
        if (p4 < CAP) g_col[d1.x * CAP + p4] = s1.x;
        if (p5 < CAP) g_col[d1.y * CAP + p5] = s1.y;
        if (p6 < CAP) g_col[d1.z * CAP + p6] = s1.z;
        if (p7 < CAP) g_col[d1.w * CAP + p7] = s1.w;
    } else {
        for (int e = e8; e < E; e++) {
            int d = dst[e];
            int p = atomicAdd(&g_cnt[d], 1);
            if (p < CAP) g_col[d * CAP + p] = src[e];
        }
    }
}

// -------------------- Prep (layer 1) + dinv + bucket pad --------------------

__global__ void k_prep(const float* __restrict__ x, int n) {
    int i = blockIdx.x * blockDim.x + threadIdx.x;   // half2 slot
    if (i >= (n + 1) * 16) return;
    int node = i >> 4, f2 = i & 15;
    float a = 0.f, b = 0.f;
    if (node < n) {
        int c = min(g_cnt[node], CAP);
        float d = rsqrtf((float)(c + 1));            // +1 self-loop
        if (f2 == 0) {
            int ce4 = (c + 3) & ~3;
            for (int s = c; s < ce4; s++) g_col[node * CAP + s] = n;  // sentinel
            g_cnte4[node] = ce4;
            g_dinv[node]  = d;
        }
        int f = f2 * 2;
        a = (f     < 25) ? d * __ldg(&x[node * 25 + f])     : 0.f;
        b = (f + 1 < 25) ? d * __ldg(&x[node * 25 + f + 1]) : 0.f;
    }
    reinterpret_cast<__half2*>(g_hA)[i] = __floats2half2_rn(a, b);
}

// ----------------------------- Aggregation ---------------------------------
// Unified shape: 4-lane groups, 8 virtual rows per warp. (node, seg) virtual
// rows, SEGS = F/32. Guard-free 4-edge unroll, int4 col prefetch, sentinel
// row n zero, HADD2 pairwise pre-add, fp32 across pairs.

template <int SEGS, int RELU, int SRC>
__global__ void k_agg_g(const float* __restrict__ bias, int n) {
    constexpr int ST = SEGS * 4;      // uint4 per full row (F/8)
    int wid  = (blockIdx.x * blockDim.x + threadIdx.x) >> 5;
    int lane = threadIdx.x & 31;
    int grp = lane >> 2;              // 0..7 virtual rows per warp
    int sub = lane & 3;               // uint4 chunk within segment
    int vrow = wid * 8 + grp;
    int node = (SEGS == 1) ? vrow : (vrow >> 1);
    int seg  = (SEGS == 1) ? 0    : (vrow & 1);
    bool valid = node < n;
    int nd = valid ? node : n;        // sentinel row safe to gather
    int so = seg * 4 + sub;           // uint4 offset within row

    const uint4* base = reinterpret_cast<const uint4*>(SRC ? g_hB : g_hA);
    __half*      db   = SRC ? g_hA : g_hB;

    float acc[8];
    {
        uint4 v = base[nd * ST + so];   // self-loop term
        float2 f0 = __half22float2(*reinterpret_cast<__half2*>(&v.x));
        float2 f1 = __half22float2(*reinterpret_cast<__half2*>(&v.y));
        float2 f2 = __half22float2(*reinterpret_cast<__half2*>(&v.z));
        float2 f3 = __half22float2(*reinterpret_cast<__half2*>(&v.w));
        acc[0] = f0.x; acc[1] = f0.y; acc[2] = f1.x; acc[3] = f1.y;
        acc[4] = f2.x; acc[5] = f2.y; acc[6] = f3.x; acc[7] = f3.y;
    }

    int e    = node * CAP;
    int endv = e + (valid ? g_cnte4[node] : 0);
    int4 jj = *reinterpret_cast<const int4*>(&g_col[e]);
    while (e < endv) {
        uint4 v0 = base[jj.x * ST + so];
        uint4 v1 = base[jj.y * ST + so];
        uint4 v2 = base[jj.z * ST + so];
        uint4 v3 = base[jj.w * ST + so];
        e += 4;
        jj = *reinterpret_cast<const int4*>(&g_col[e]);   // prefetch (spare bucket)
        __half2 a0 = __hadd2(*reinterpret_cast<__half2*>(&v0.x), *reinterpret_cast<__half2*>(&v1.x));
        __half2 a1 = __hadd2(*reinterpret_cast<__half2*>(&v0.y), *reinterpret_cast<__half2*>(&v1.y));
        __half2 a2 = __hadd2(*reinterpret_cast<__half2*>(&v0.z), *reinterpret_cast<__half2*>(&v1.z));
        __half2 a3 = __hadd2(*reinterpret_cast<__half2*>(&v0.w), *reinterpret_cast<__half2*>(&v1.w));
        __half2 b0 = __hadd2(*reinterpret_cast<__half2*>(&v2.x), *reinterpret_cast<__half2*>(&v3.x));
        __half2 b1 = __hadd2(*reinterpret_cast<__half2*>(&v2.y), *reinterpret_cast<__half2*>(&v3.y));
        __half2 b2 = __hadd2(*reinterpret_cast<__half2*>(&v2.z), *reinterpret_cast<__half2*>(&v3.z));
        __half2 b3 = __hadd2(*reinterpret_cast<__half2*>(&v2.w), *reinterpret_cast<__half2*>(&v3.w));
        float2 fa0 = __half22float2(a0), fa1 = __half22float2(a1);
        float2 fa2 = __half22float2(a2), fa3 = __half22float2(a3);
        float2 fb0 = __half22float2(b0), fb1 = __half22float2(b1);
        float2 fb2 = __half22float2(b2), fb3 = __half22float2(b3);
        acc[0] += fa0.x + fb0.x; acc[1] += fa0.y + fb0.y;
        acc[2] += fa1.x + fb1.x; acc[3] += fa1.y + fb1.y;
        acc[4] += fa2.x + fb2.x; acc[5] += fa2.y + fb2.y;
        acc[6] += fa3.x + fb3.x; acc[7] += fa3.y + fb3.y;
    }

    if (valid) {
        float d = g_dinv[node];
        __half out[8];
#pragma unroll
        for (int k = 0; k < 8; k++) {
            float r;
            if (RELU) r = fmaxf(fmaf(acc[k], d, __ldg(&bias[seg * 32 + sub * 8 + k])), 0.f);
            else      r = acc[k] * d;
            out[k] = __float2half_rn(r);
        }
        reinterpret_cast<uint4*>(db)[node * ST + so] = *reinterpret_cast<uint4*>(out);
    }
}

// ------------------------------- Dense GEMM --------------------------------
// 4 rows per thread: each W smem load amortized over 4 accumulator chains
// (R15 ncu: gemm was LDS-bound at L1=72%). Block 0 writes zero sentinel row n.

template <int FINP, int FINW, int FOUT, int EPI, int SRC>
__global__ void k_gemm_h(const float* __restrict__ W, const float* __restrict__ bias, int n) {
    __shared__ float Wsh[FINP * FOUT];
    for (int i = threadIdx.x; i < FINP * FOUT; i += blockDim.x)
        Wsh[i] = (i < FINW * FOUT) ? W[i] : 0.f;
    __syncthreads();

    const __half* X = SRC ? g_hB : g_hA;
    __half*       O = SRC ? g_hA : g_hB;

    if (blockIdx.x == 0 && threadIdx.x < FOUT / 8) {   // zero sentinel row n
        reinterpret_cast<uint4*>(O)[(long)n * (FOUT / 8) + threadIdx.x] =
            make_uint4(0u, 0u, 0u, 0u);
    }

    constexpr int TPR  = FOUT / 4;
    constexpr int RPB  = 256 / TPR;
    constexpr int RPB4 = RPB * 4;
    int slot = (int)(threadIdx.x / TPR);
    int fx = (threadIdx.x % TPR) * 4;
    int rbase = blockIdx.x * RPB4 + slot;
    int row[4];
    bool vld[4];
    const uint4* xr[4];
#pragma unroll
    for (int r = 0; r < 4; r++) {
        row[r] = rbase + r * RPB;
        vld[r] = row[r] < n;
        xr[r]  = reinterpret_cast<const uint4*>(X + (long)(vld[r] ? row[r] : 0) * FINP);
    }
    if (!vld[0]) return;

    float4 a0 = make_float4(0.f, 0.f, 0.f, 0.f);
    float4 a1 = a0, a2 = a0, a3 = a0;
#pragma unroll
    for (int q = 0; q < FINP / 8; q++) {
        uint4 p0 = __ldg(&xr[0][q]);
        uint4 p1 = __ldg(&xr[1][q]);
        uint4 p2 = __ldg(&xr[2][q]);
        uint4 p3 = __ldg(&xr[3][q]);
        const unsigned* u0 = &p0.x;
        const unsigned* u1 = &p1.x;
        const unsigned* u2 = &p2.x;
        const unsigned* u3 = &p3.x;
#pragma unroll
        for (int t = 0; t < 4; t++) {
            float2 f0 = __half22float2(*reinterpret_cast<const __half2*>(&u0[t]));
            float2 f1 = __half22float2(*reinterpret_cast<const __half2*>(&u1[t]));
            float2 f2 = __half22float2(*reinterpret_cast<const __half2*>(&u2[t]));
            float2 f3 = __half22float2(*reinterpret_cast<const __half2*>(&u3[t]));
            int k = q * 8 + t * 2;
            float4 w0 = *reinterpret_cast<const float4*>(&Wsh[k * FOUT + fx]);
            float4 w1 = *reinterpret_cast<const float4*>(&Wsh[(k + 1) * FOUT + fx]);
            a0.x = fmaf(f0.x, w0.x, fmaf(f0.y, w1.x, a0.x));
            a0.y = fmaf(f0.x, w0.y, fmaf(f0.y, w1.y, a0.y));
            a0.z = fmaf(f0.x, w0.z, fmaf(f0.y, w1.z, a0.z));
            a0.w = fmaf(f0.x, w0.w, fmaf(f0.y, w1.w, a0.w));
            a1.x = fmaf(f1.x, w0.x, fmaf(f1.y, w1.x, a1.x));
            a1.y = fmaf(f1.x, w0.y, fmaf(f1.y, w1.y, a1.y));
            a1.z = fmaf(f1.x, w0.z, fmaf(f1.y, w1.z, a1.z));
            a1.w = fmaf(f1.x, w0.w, fmaf(f1.y, w1.w, a1.w));
            a2.x = fmaf(f2.x, w0.x, fmaf(f2.y, w1.x, a2.x));
            a2.y = fmaf(f2.x, w0.y, fmaf(f2.y, w1.y, a2.y));
            a2.z = fmaf(f2.x, w0.z, fmaf(f2.y, w1.z, a2.z));
            a2.w = fmaf(f2.x, w0.w, fmaf(f2.y, w1.w, a2.w));
            a3.x = fmaf(f3.x, w0.x, fmaf(f3.y, w1.x, a3.x));
            a3.y = fmaf(f3.x, w0.y, fmaf(f3.y, w1.y, a3.y));
            a3.z = fmaf(f3.x, w0.z, fmaf(f3.y, w1.z, a3.z));
            a3.w = fmaf(f3.x, w0.w, fmaf(f3.y, w1.w, a3.w));
        }
    }

    float bx = 0.f, by = 0.f, bz = 0.f, bw = 0.f;
    if (EPI == 1) {
        bx = __ldg(&bias[fx + 0]); by = __ldg(&bias[fx + 1]);
        bz = __ldg(&bias[fx + 2]); bw = __ldg(&bias[fx + 3]);
    }
    float4 accs[4] = {a0, a1, a2, a3};
#pragma unroll
    for (int r = 0; r < 4; r++) {
        if (!vld[r]) break;
        float4 acc = accs[r];
        if (EPI == 0) {
            float d = g_dinv[row[r]];
            acc.x *= d; acc.y *= d; acc.z *= d; acc.w *= d;
        } else {
            acc.x = fmaxf(acc.x + bx, 0.f); acc.y = fmaxf(acc.y + by, 0.f);
            acc.z = fmaxf(acc.z + bz, 0.f); acc.w = fmaxf(acc.w + bw, 0.f);
        }
        __half2* op = reinterpret_cast<__half2*>(&O[(long)row[r] * FOUT + fx]);
        op[0] = __floats2half2_rn(acc.x, acc.y);
        op[1] = __floats2half2_rn(acc.z, acc.w);
    }
}

// ------------------------- Pool + MLP head (fused) --------------------------

__global__ void k_pool_mlp(const int* __restrict__ batch, int n,
                           const float* __restrict__ Wh1, const float* __restrict__ bh1,
                           const float* __restrict__ Wh2, const float* __restrict__ bh2,
                           float* __restrict__ out) {
    int g = blockIdx.x;
    int lo = 0, hi = n;
    while (lo < hi) { int mid = (lo + hi) >> 1; if (batch[mid] < g) lo = mid + 1; else hi = mid; }
    int start = lo;
    hi = n;
    while (lo < hi) { int mid = (lo + hi) >> 1; if (batch[mid] < g + 1) lo = mid + 1; else hi = mid; }
    int end = lo;

    __shared__ float partial[4][32];
    __shared__ float gsum[32];
    int f = threadIdx.x & 31;
    int r = threadIdx.x >> 5;
    float acc = 0.f;
    for (int i = start + r; i < end; i += 4) acc += __half2float(g_hA[(long)i * 32 + f]);
    partial[r][f] = acc;
    __syncthreads();

    if (threadIdx.x < 32) {
        float s = partial[0][f] + partial[1][f] + partial[2][f] + partial[3][f];
        float cnt = (float)((end - start) > 0 ? (end - start) : 1);
        gsum[f] = s / cnt;
    }
    __syncthreads();

    if (threadIdx.x < 32) {
        int o = threadIdx.x;
        float h = bh1[o];
#pragma unroll
        for (int k = 0; k < 32; k++) h = fmaf(gsum[k], Wh1[k * 32 + o], h);
        h = fmaxf(h, 0.f);
        float y = h * Wh2[o];
#pragma unroll
        for (int off = 16; off; off >>= 1) y += __shfl_down_sync(0xffffffffu, y, off);
        if (o == 0) out[g] = y + bh2[0];
    }
}

// ------------------------------- Launcher ----------------------------------

extern "C" void kernel_launch(void* const* d_in, const int* in_sizes, int n_in,
                              void* d_out, int out_size) {
    const float* x     = (const float*)d_in[0];
    const int*   ei    = (const int*)d_in[1];
    const int*   batch = (const int*)d_in[2];
    const float* W1  = (const float*)d_in[3];
    const float* b1  = (const float*)d_in[4];
    const float* W2  = (const float*)d_in[5];
    const float* b2  = (const float*)d_in[6];
    const float* W3  = (const float*)d_in[7];
    const float* b3  = (const float*)d_in[8];
    const float* Wh1 = (const float*)d_in[9];
    const float* bh1 = (const float*)d_in[10];
    const float* Wh2 = (const float*)d_in[11];
    const float* bh2 = (const float*)d_in[12];
    float* out = (float*)d_out;

    int N = in_sizes[0] / 25;
    int E = in_sizes[1] / 2;
    const int* src = ei;
    const int* dst = ei + E;

    int nThreads = 256;
    int nBlkE8 = (E + nThreads * 8 - 1) / (nThreads * 8);
    int agg1Blocks = (N + 63) / 64;          // SEGS=1: 8 nodes/warp
    int agg2Blocks = (2 * N + 63) / 64;      // SEGS=2: 2N virtual rows

    // --- Clear counters ---
    void* p = nullptr;
    cudaGetSymbolAddress(&p, g_cnt);
    cudaMemsetAsync(p, 0, N * sizeof(int));

    // --- Bucket adjacency build (single edge pass) ---
    k_fill<<<nBlkE8, nThreads>>>(src, dst, E);

    // --- Layer 1: prep (+dinv+pad) -> aggregate -> 25->64 GEMM ---
    k_prep<<<((N + 1) * 16 + 255) / 256, 256>>>(x, N);        // x -> A (+sentinel)
    k_agg_g<1, 0, 0><<<agg1Blocks, 256>>>(nullptr, N);        // A -> B
    k_gemm_h<32, 25, 64, 1, 1><<<(N + 63) / 64, 256>>>(W1, b1, N);  // B -> A

    // --- Layer 2 ---
    k_gemm_h<64, 64, 64, 0, 0><<<(N + 63) / 64, 256>>>(W2, nullptr, N);   // A -> B (+sentinel@64)
    k_agg_g<2, 1, 1><<<agg2Blocks, 256>>>(b2, N);                         // B -> A

    // --- Layer 3 ---
    k_gemm_h<64, 64, 32, 0, 0><<<(N + 127) / 128, 256>>>(W3, nullptr, N); // A -> B (+sentinel@32)
    k_agg_g<1, 1, 1><<<agg1Blocks, 256>>>(b3, N);                         // B -> A

    // --- Pool + MLP head ---
    k_pool_mlp<<<GMAX, 128>>>(batch, N, Wh1, bh1, Wh2, bh2, out);
}